// round 1
// baseline (speedup 1.0000x reference)
#include <cuda_runtime.h>
#include <cuda_bf16.h>
#include <mma.h>
#include <cstdint>

using namespace nvcuda;

#define T_TOK 16384
#define H_DIM 1024
#define H2_DIM 2048
#define NEXP 8

#define BM 128
#define BN 128
#define BK 16

// ---------------- scratch (device globals; no allocation) ----------------
__device__ float g_hdn[2 * T_TOK * H2_DIM];   // [2T][2048] bucket-contiguous
__device__ float g_y  [2 * T_TOK * H_DIM];    // [2T][1024] bucket-contiguous
__device__ int   g_counts [NEXP];
__device__ int   g_offsets[NEXP];
__device__ int   g_bucket [NEXP * T_TOK];     // per expert: slot = (tok<<1)|k
__device__ float g_wt [2 * T_TOK];
__device__ int   g_pos[2 * T_TOK];
__device__ int   g_eid[2 * T_TOK];

// ---------------- kernels ----------------
__global__ void zero_counts_kernel() {
    if (threadIdx.x < NEXP) g_counts[threadIdx.x] = 0;
}

// one warp per token: 8 logit dot-products, softmax top-2, bucket scatter
__global__ void router_kernel(const float* __restrict__ x,
                              const float* __restrict__ gate) {
    int w    = threadIdx.x >> 5;
    int lane = threadIdx.x & 31;
    int t = blockIdx.x * 8 + w;
    if (t >= T_TOK) return;
    const float* xp = x + (size_t)t * H_DIM;

    float acc[NEXP];
#pragma unroll
    for (int e = 0; e < NEXP; e++) acc[e] = 0.f;

    for (int h = lane; h < H_DIM; h += 32) {
        float xv = xp[h];
        const float4* gp = (const float4*)(gate + h * NEXP);
        float4 ga = gp[0], gb = gp[1];
        acc[0] += xv * ga.x; acc[1] += xv * ga.y;
        acc[2] += xv * ga.z; acc[3] += xv * ga.w;
        acc[4] += xv * gb.x; acc[5] += xv * gb.y;
        acc[6] += xv * gb.z; acc[7] += xv * gb.w;
    }
#pragma unroll
    for (int e = 0; e < NEXP; e++) {
        float v = acc[e];
#pragma unroll
        for (int off = 16; off; off >>= 1) v += __shfl_xor_sync(0xffffffffu, v, off);
        acc[e] = v;
    }
    if (lane == 0) {
        // top-2 with first-index tie-break (matches jax.lax.top_k)
        float best = -1e30f; int bi = 0;
#pragma unroll
        for (int e = 0; e < NEXP; e++) if (acc[e] > best) { best = acc[e]; bi = e; }
        float sec = -1e30f; int si = 0;
#pragma unroll
        for (int e = 0; e < NEXP; e++) if (e != bi && acc[e] > sec) { sec = acc[e]; si = e; }
        // normalized softmax pair: w0 = p0/(p0+p1) = 1/(1+exp(l1-l0))
        float w0  = 1.f / (1.f + expf(sec - best));
        float w1n = 1.f - w0;

        int p0 = atomicAdd(&g_counts[bi], 1);
        g_bucket[bi * T_TOK + p0] = (t << 1);
        int p1 = atomicAdd(&g_counts[si], 1);
        g_bucket[si * T_TOK + p1] = (t << 1) | 1;

        g_wt [2 * t] = w0;  g_wt [2 * t + 1] = w1n;
        g_eid[2 * t] = bi;  g_eid[2 * t + 1] = si;
        g_pos[2 * t] = p0;  g_pos[2 * t + 1] = p1;
    }
}

__global__ void offsets_kernel() {
    if (threadIdx.x == 0) {
        int s = 0;
        for (int e = 0; e < NEXP; e++) { g_offsets[e] = s; s += g_counts[e]; }
    }
}

// Grouped GEMM, TF32 wmma 16x16x8. Block tile 128x128, BK=16, 8 warps,
// each warp 64x32 (4x2 fragments).
// PHASE1: A = gathered token rows from x [*,1024], W = w1[e] [1024,2048],
//         C = relu(A@W + b1) -> g_hdn (bucket-contiguous rows)
// else:   A = g_hdn rows (contiguous),  W = w2[e] [2048,1024],
//         C = A@W + b2 -> g_y
template<int KDIM, int NDIM, bool PHASE1>
__global__ void __launch_bounds__(256)
grouped_gemm_kernel(const float* __restrict__ xflat,
                    const float* __restrict__ Wbase,
                    const float* __restrict__ Bias) {
    int e   = blockIdx.z;
    int cnt = g_counts[e];
    int m0  = blockIdx.x * BM;
    if (m0 >= cnt) return;
    int n0    = blockIdx.y * BN;
    int obase = g_offsets[e];

    __shared__ float As[BM][20];          // padded, ld=20 (16B-mult fragments)
    __shared__ float Bs[BK][BN + 4];      // ld=132
    __shared__ int   rowsrc[BM];
    __shared__ float stage[8][16][20];    // per-warp epilogue staging

    int tid = threadIdx.x;
    for (int i = tid; i < BM; i += 256) {
        int r = m0 + i;
        if (PHASE1)
            rowsrc[i] = (r < cnt) ? (g_bucket[e * T_TOK + r] >> 1) : -1;
        else
            rowsrc[i] = (r < cnt) ? (obase + r) : -1;
    }
    __syncthreads();

    const float* Abase = PHASE1 ? xflat : g_hdn;
    const float* We    = Wbase + (size_t)e * KDIM * NDIM;

    int w    = tid >> 5;
    int lane = tid & 31;
    int wm   = w >> 2;    // 0..1 -> 64 rows each
    int wn   = w & 3;     // 0..3 -> 32 cols each

    wmma::fragment<wmma::accumulator, 16, 16, 8, float> c[4][2];
#pragma unroll
    for (int fm = 0; fm < 4; fm++)
#pragma unroll
        for (int fn = 0; fn < 2; fn++) wmma::fill_fragment(c[fm][fn], 0.f);

    for (int kb = 0; kb < KDIM; kb += BK) {
        // A: 128x16 floats = 512 float4, 2 per thread
#pragma unroll
        for (int j = 0; j < 2; j++) {
            int idx = tid + j * 256;
            int row = idx >> 2;
            int c4  = idx & 3;
            int src = rowsrc[row];
            float4 v = make_float4(0.f, 0.f, 0.f, 0.f);
            if (src >= 0)
                v = *(const float4*)(Abase + (size_t)src * KDIM + kb + c4 * 4);
            float* dst = &As[row][c4 * 4];
            dst[0] = wmma::__float_to_tf32(v.x);
            dst[1] = wmma::__float_to_tf32(v.y);
            dst[2] = wmma::__float_to_tf32(v.z);
            dst[3] = wmma::__float_to_tf32(v.w);
        }
        // B: 16x128 floats = 512 float4, 2 per thread
#pragma unroll
        for (int j = 0; j < 2; j++) {
            int idx = tid + j * 256;
            int row = idx >> 5;     // 0..15
            int c4  = idx & 31;
            float4 v = *(const float4*)(We + (size_t)(kb + row) * NDIM + n0 + c4 * 4);
            float* dst = &Bs[row][c4 * 4];
            dst[0] = wmma::__float_to_tf32(v.x);
            dst[1] = wmma::__float_to_tf32(v.y);
            dst[2] = wmma::__float_to_tf32(v.z);
            dst[3] = wmma::__float_to_tf32(v.w);
        }
        __syncthreads();

#pragma unroll
        for (int ks = 0; ks < 2; ks++) {
            wmma::fragment<wmma::matrix_a, 16, 16, 8, wmma::precision::tf32, wmma::row_major> a[4];
            wmma::fragment<wmma::matrix_b, 16, 16, 8, wmma::precision::tf32, wmma::row_major> b[2];
#pragma unroll
            for (int fm = 0; fm < 4; fm++)
                wmma::load_matrix_sync(a[fm], &As[wm * 64 + fm * 16][ks * 8], 20);
#pragma unroll
            for (int fn = 0; fn < 2; fn++)
                wmma::load_matrix_sync(b[fn], &Bs[ks * 8][wn * 32 + fn * 16], BN + 4);
#pragma unroll
            for (int fm = 0; fm < 4; fm++)
#pragma unroll
                for (int fn = 0; fn < 2; fn++)
                    wmma::mma_sync(c[fm][fn], a[fm], b[fn], c[fm][fn]);
        }
        __syncthreads();
    }

    // epilogue: bias (+relu), rows bucket-contiguous
    float* Cbase = PHASE1 ? g_hdn : g_y;
#pragma unroll
    for (int fm = 0; fm < 4; fm++) {
#pragma unroll
        for (int fn = 0; fn < 2; fn++) {
            wmma::store_matrix_sync(&stage[w][0][0], c[fm][fn], 20, wmma::mem_row_major);
            __syncwarp();
            int r  = lane >> 1;
            int c0 = (lane & 1) * 8;
            int rexp = m0 + wm * 64 + fm * 16 + r;
            if (rexp < cnt) {
                int grow = obase + rexp;
                int gcol = n0 + wn * 32 + fn * 16 + c0;
                float*       outp = Cbase + (size_t)grow * NDIM + gcol;
                const float* bp   = Bias  + (size_t)e    * NDIM + gcol;
#pragma unroll
                for (int q = 0; q < 8; q++) {
                    float v = stage[w][r][c0 + q] + bp[q];
                    if (PHASE1) v = fmaxf(v, 0.f);
                    outp[q] = v;
                }
            }
            __syncwarp();
        }
    }
}

// one block per token: out[t] = w0*y[row0] + w1*y[row1]  (deterministic order)
__global__ void combine_kernel(float* __restrict__ out) {
    int t   = blockIdx.x;
    int tid = threadIdx.x;
    __shared__ float sw0, sw1;
    __shared__ int   srow0, srow1;
    if (tid == 0) {
        int e0 = g_eid[2 * t], e1 = g_eid[2 * t + 1];
        srow0 = g_offsets[e0] + g_pos[2 * t];
        srow1 = g_offsets[e1] + g_pos[2 * t + 1];
        sw0 = g_wt[2 * t]; sw1 = g_wt[2 * t + 1];
    }
    __syncthreads();
    const float4* y0 = (const float4*)(g_y + (size_t)srow0 * H_DIM);
    const float4* y1 = (const float4*)(g_y + (size_t)srow1 * H_DIM);
    float4* op = (float4*)(out + (size_t)t * H_DIM);
    float w0 = sw0, w1 = sw1;
    float4 a = y0[tid], b = y1[tid];
    float4 r;
    r.x = w0 * a.x + w1 * b.x;
    r.y = w0 * a.y + w1 * b.y;
    r.z = w0 * a.z + w1 * b.z;
    r.w = w0 * a.w + w1 * b.w;
    op[tid] = r;
}

// ---------------- launch ----------------
extern "C" void kernel_launch(void* const* d_in, const int* in_sizes, int n_in,
                              void* d_out, int out_size) {
    const float* x    = (const float*)d_in[0];  // [4,4096,1024]
    const float* gate = (const float*)d_in[1];  // [1024,8]
    const float* w1   = (const float*)d_in[2];  // [8,1024,2048]
    const float* b1   = (const float*)d_in[3];  // [8,2048]
    const float* w2   = (const float*)d_in[4];  // [8,2048,1024]
    const float* b2   = (const float*)d_in[5];  // [8,1024]
    float* out = (float*)d_out;
    (void)in_sizes; (void)n_in; (void)out_size;

    zero_counts_kernel<<<1, 32>>>();
    router_kernel<<<T_TOK / 8, 256>>>(x, gate);
    offsets_kernel<<<1, 32>>>();

    {
        dim3 g(T_TOK / BM, H2_DIM / BN, NEXP);
        grouped_gemm_kernel<H_DIM, H2_DIM, true><<<g, 256>>>(x, w1, b1);
    }
    {
        dim3 g(T_TOK / BM, H_DIM / BN, NEXP);
        grouped_gemm_kernel<H2_DIM, H_DIM, false><<<g, 256>>>(x, w2, b2);
    }
    combine_kernel<<<T_TOK, 256>>>(out);
}